// round 4
// baseline (speedup 1.0000x reference)
#include <cuda_runtime.h>
#include <cstdint>
#include <math.h>

#define BB 64
#define TT 1024
#define HH 512
#define G3 1536
#define WS_PAD 516

// ---------------- scratch (device globals; no runtime allocation) ----------------
__device__ float g_xg[(size_t)BB * TT * G3];   // [B*T][1536] packed input-gate projections
__device__ float g_y0[(size_t)BB * TT * HH];   // [B*T][512] layer-0 tanh outputs (layer-1 reuses first 64*512 for last-step tanh)
__device__ float g_h[2][BB * HH];              // ping-pong hidden state
__device__ unsigned g_bar_arrive;
__device__ unsigned g_bar_release;

// ---------------- grid-wide barrier (all 128 CTAs resident, 1/SM) ----------------
__device__ __forceinline__ void gbar(unsigned gen) {
    __syncthreads();
    if (threadIdx.x == 0) {
        __threadfence();
        unsigned a = atomicAdd(&g_bar_arrive, 1u) + 1u;
        if (a == gen * 128u) {
            atomicExch(&g_bar_release, gen);
        } else {
            while ((int)(*(volatile unsigned*)&g_bar_release - gen) < 0)
                __nanosleep(32);
        }
        __threadfence();
    }
    __syncthreads();
}

// ---------------- phase A: C[M,1536] = A[M,K] @ W[K,1536] + bias ----------------
__global__ __launch_bounds__(256) void gemm_k(
    const float* __restrict__ A, const float* __restrict__ W,
    const float* __restrict__ bias, float* __restrict__ C, int K)
{
    __shared__ float As[16][136];   // As[k][m]
    __shared__ float Bs[16][128];   // Bs[k][n]
    const int tid = threadIdx.x;
    const int bm = blockIdx.y * 128;
    const int bn = blockIdx.x * 128;
    const int tm = (tid >> 4) << 3;
    const int tn = (tid & 15) << 3;

    const int ar = tid >> 1;           // 0..127 (A row)
    const int ac = (tid & 1) << 3;     // 0 or 8 (k offset)
    const int br = tid >> 5;           // 0..7   (W k row)
    const int bc = (tid & 31) << 2;    // 0..124 (W col)

    float acc[8][8];
#pragma unroll
    for (int i = 0; i < 8; ++i)
#pragma unroll
        for (int j = 0; j < 8; ++j) acc[i][j] = 0.f;

    for (int k0 = 0; k0 < K; k0 += 16) {
        float4 a0 = *(const float4*)&A[(size_t)(bm + ar) * K + k0 + ac];
        float4 a1 = *(const float4*)&A[(size_t)(bm + ar) * K + k0 + ac + 4];
        float4 b0 = *(const float4*)&W[(size_t)(k0 + br) * G3 + bn + bc];
        float4 b1 = *(const float4*)&W[(size_t)(k0 + br + 8) * G3 + bn + bc];
        __syncthreads();
        As[ac + 0][ar] = a0.x; As[ac + 1][ar] = a0.y;
        As[ac + 2][ar] = a0.z; As[ac + 3][ar] = a0.w;
        As[ac + 4][ar] = a1.x; As[ac + 5][ar] = a1.y;
        As[ac + 6][ar] = a1.z; As[ac + 7][ar] = a1.w;
        *(float4*)&Bs[br][bc]     = b0;
        *(float4*)&Bs[br + 8][bc] = b1;
        __syncthreads();
#pragma unroll
        for (int kk = 0; kk < 16; ++kk) {
            float4 af0 = *(const float4*)&As[kk][tm];
            float4 af1 = *(const float4*)&As[kk][tm + 4];
            float4 bf0 = *(const float4*)&Bs[kk][tn];
            float4 bf1 = *(const float4*)&Bs[kk][tn + 4];
            float av[8] = {af0.x, af0.y, af0.z, af0.w, af1.x, af1.y, af1.z, af1.w};
            float bv[8] = {bf0.x, bf0.y, bf0.z, bf0.w, bf1.x, bf1.y, bf1.z, bf1.w};
#pragma unroll
            for (int i = 0; i < 8; ++i)
#pragma unroll
                for (int j = 0; j < 8; ++j)
                    acc[i][j] = fmaf(av[i], bv[j], acc[i][j]);
        }
    }
    float bvv[8];
#pragma unroll
    for (int j = 0; j < 8; ++j) bvv[j] = bias[bn + tn + j];
#pragma unroll
    for (int i = 0; i < 8; ++i) {
        float* cp = &C[(size_t)(bm + tm + i) * G3 + bn + tn];
        float4 v0 = make_float4(acc[i][0] + bvv[0], acc[i][1] + bvv[1],
                                acc[i][2] + bvv[2], acc[i][3] + bvv[3]);
        float4 v1 = make_float4(acc[i][4] + bvv[4], acc[i][5] + bvv[5],
                                acc[i][6] + bvv[6], acc[i][7] + bvv[7]);
        *(float4*)&cp[0] = v0;
        *(float4*)&cp[4] = v1;
    }
}

// ---------------- phase R: persistent GRU recurrence ----------------
// 128 CTAs = 4 batch-groups(16) x 32 col-groups(16 output cols = 48 gate cols).
// smem: Ws[48][516] weight slice (cached all steps), hs[16][516] h tile, red partials.
#define SMEM_R ((48 * WS_PAD + 16 * WS_PAD + 8 * 16 * 16 * 3) * 4)

__device__ __forceinline__ float sigf(float x) { return 1.f / (1.f + expf(-x)); }

__global__ __launch_bounds__(256, 1) void gru_rec(
    const float* __restrict__ Wh,    // [512][1536]
    const float* __restrict__ bhn,   // [512]
    const float* __restrict__ xg,    // [B*T][1536]
    float* __restrict__ y,           // [B*T][512] (y_all=1) or [B][512] last-step tanh (y_all=0)
    float* __restrict__ cfin,        // [64*512] final raw h
    int y_all)
{
    extern __shared__ float sm[];
    float* Ws  = sm;                       // [48][WS_PAD], row c = g*16 + jl
    float* hs  = Ws + 48 * WS_PAD;         // [16][WS_PAD]
    float* red = hs + 16 * WS_PAD;         // [8 kc][16 b][16 j][3 g]

    const int tid = threadIdx.x;
    const int cta = blockIdx.x;
    const int b0 = (cta >> 5) * 16;
    const int j0 = (cta & 31) * 16;

    // Stage W_h slice once (reused for all 1024 steps).
    for (int i = tid; i < 48 * 512; i += 256) {
        int k = i / 48;
        int c = i % 48;
        int g = c >> 4, jl = c & 15;
        Ws[c * WS_PAD + k] = Wh[(size_t)k * G3 + g * HH + j0 + jl];
    }

    unsigned gen = *(volatile unsigned*)&g_bar_release;
    g_h[0][cta * 256 + tid] = 0.f;         // h0 = 0 (exactly covers 64*512)
    gbar(++gen);

    const int jl = tid & 15;
    const int bh = (tid >> 4) & 1;         // batch half (8 each)
    const int kc = tid >> 5;               // K-split 0..7
    const int kb = kc * 64;
    const int eb = tid >> 4;               // elementwise batch 0..15
    const int ej = tid & 15;               // elementwise col
    const float bh_n = bhn[j0 + ej];

    for (int t = 0; t < TT; ++t) {
        const float* hin = g_h[t & 1];
        float* hout = g_h[(t + 1) & 1];

        // Early xg prefetch (DRAM stream), consumed in elementwise phase.
        size_t xi = ((size_t)(b0 + eb) * TT + t) * G3 + j0 + ej;
        float xr = __ldcs(&xg[xi]);
        float xz = __ldcs(&xg[xi + 512]);
        float xn = __ldcs(&xg[xi + 1024]);

        // Stage h tile (16 x 512) from L2 (coherent, bypass L1).
#pragma unroll
        for (int u = 0; u < 8; ++u) {
            int i = tid + u * 256;
            int b = i >> 7;
            int k4 = (i & 127) << 2;
            float4 v = __ldcg((const float4*)&hin[(size_t)(b0 + b) * HH + k4]);
            *(float4*)&hs[b * WS_PAD + k4] = v;
        }
        __syncthreads();

        // Partial GEMM: acc[8 batches][3 gates], K chunk of 64.
        float acc[8][3];
#pragma unroll
        for (int i = 0; i < 8; ++i)
            acc[i][0] = acc[i][1] = acc[i][2] = 0.f;

        const float* w0p = &Ws[(0 * 16 + jl) * WS_PAD];
        const float* w1p = &Ws[(1 * 16 + jl) * WS_PAD];
        const float* w2p = &Ws[(2 * 16 + jl) * WS_PAD];
        const float* hp  = &hs[bh * 8 * WS_PAD];

#pragma unroll 4
        for (int k4 = kb; k4 < kb + 64; k4 += 4) {
            float4 w0 = *(const float4*)&w0p[k4];
            float4 w1 = *(const float4*)&w1p[k4];
            float4 w2 = *(const float4*)&w2p[k4];
#pragma unroll
            for (int i = 0; i < 8; ++i) {
                float4 hv = *(const float4*)&hp[i * WS_PAD + k4];
                acc[i][0] = fmaf(hv.x, w0.x, fmaf(hv.y, w0.y, fmaf(hv.z, w0.z, fmaf(hv.w, w0.w, acc[i][0]))));
                acc[i][1] = fmaf(hv.x, w1.x, fmaf(hv.y, w1.y, fmaf(hv.z, w1.z, fmaf(hv.w, w1.w, acc[i][1]))));
                acc[i][2] = fmaf(hv.x, w2.x, fmaf(hv.y, w2.y, fmaf(hv.z, w2.z, fmaf(hv.w, w2.w, acc[i][2]))));
            }
        }

        // Write K-split partials.
#pragma unroll
        for (int i = 0; i < 8; ++i) {
            int b = bh * 8 + i;
            float* rp = &red[((kc * 16 + b) * 16 + jl) * 3];
            rp[0] = acc[i][0]; rp[1] = acc[i][1]; rp[2] = acc[i][2];
        }
        __syncthreads();

        // Elementwise GRU update: thread = (eb, ej).
        float hr = 0.f, hz = 0.f, hn = 0.f;
#pragma unroll
        for (int c = 0; c < 8; ++c) {
            const float* rp = &red[((c * 16 + eb) * 16 + ej) * 3];
            hr += rp[0]; hz += rp[1]; hn += rp[2];
        }
        float h_old = hs[eb * WS_PAD + j0 + ej];
        float r = sigf(xr + hr);
        float z = sigf(xz + hz);
        float n = tanhf(xn + r * (hn + bh_n));
        float hnew = (1.f - z) * n + z * h_old;

        hout[(size_t)(b0 + eb) * HH + j0 + ej] = hnew;
        if (y_all) {
            y[((size_t)(b0 + eb) * TT + t) * HH + j0 + ej] = tanhf(hnew);
        } else if (t == TT - 1) {
            y[(size_t)(b0 + eb) * HH + j0 + ej] = tanhf(hnew);
        }
        if (t == TT - 1)
            cfin[(size_t)(b0 + eb) * HH + j0 + ej] = hnew;

        gbar(++gen);
    }
}

// ---------------- dense head: out = tanh(ylast @ W_out + b_out) ----------------
__global__ __launch_bounds__(256) void dense_k(
    const float* __restrict__ yl,    // [64][512] (already tanh'd)
    const float* __restrict__ W,     // [512][512]
    const float* __restrict__ b,     // [512]
    float* __restrict__ out)         // [64][512]
{
    int gid = blockIdx.x * 256 + threadIdx.x;   // 32768 = 64*512
    int bb = gid >> 9;
    int j  = gid & 511;
    const float* xr = yl + (size_t)bb * 512;
    float s = b[j];
#pragma unroll 4
    for (int k = 0; k < 512; k += 4) {
        float4 xv = *(const float4*)&xr[k];
        s = fmaf(xv.x, W[(size_t)(k + 0) * 512 + j], s);
        s = fmaf(xv.y, W[(size_t)(k + 1) * 512 + j], s);
        s = fmaf(xv.z, W[(size_t)(k + 2) * 512 + j], s);
        s = fmaf(xv.w, W[(size_t)(k + 3) * 512 + j], s);
    }
    out[gid] = tanhf(s);
}

// ---------------- launch ----------------
extern "C" void kernel_launch(void* const* d_in, const int* in_sizes, int n_in,
                              void* d_out, int out_size) {
    const float* x     = (const float*)d_in[0];
    const float* W_i0  = (const float*)d_in[1];
    const float* b_i0  = (const float*)d_in[2];
    const float* W_h0  = (const float*)d_in[3];
    const float* b_hn0 = (const float*)d_in[4];
    const float* W_i1  = (const float*)d_in[5];
    const float* b_i1  = (const float*)d_in[6];
    const float* W_h1  = (const float*)d_in[7];
    const float* b_hn1 = (const float*)d_in[8];
    const float* W_out = (const float*)d_in[9];
    const float* b_out = (const float*)d_in[10];

    float* out = (float*)d_out;               // [64,512]
    float* c0  = out + 64 * 512;              // [64,512]
    float* c1  = c0 + 64 * 512;               // [64,512]

    cudaFuncSetAttribute(gru_rec, cudaFuncAttributeMaxDynamicSharedMemorySize, SMEM_R);

    float* xg;  cudaGetSymbolAddress((void**)&xg, g_xg);
    float* y0;  cudaGetSymbolAddress((void**)&y0, g_y0);

    dim3 ggrid(G3 / 128, (BB * TT) / 128);

    // Layer 0
    gemm_k<<<ggrid, 256>>>(x, W_i0, b_i0, xg, 256);
    gru_rec<<<128, 256, SMEM_R>>>(W_h0, b_hn0, xg, y0, c0, 1);
    // Layer 1
    gemm_k<<<ggrid, 256>>>(y0, W_i1, b_i1, xg, 512);
    gru_rec<<<128, 256, SMEM_R>>>(W_h1, b_hn1, xg, y0 /*last-step tanh*/, c1, 0);
    // Dense head
    dense_k<<<128, 256>>>(y0, W_out, b_out, out);
}

// round 5
// speedup vs baseline: 1.0498x; 1.0498x over previous
#include <cuda_runtime.h>
#include <cstdint>
#include <math.h>

#define BB 64
#define TT 1024
#define HH 512
#define G3 1536
#define WS_PAD 516

// ---------------- scratch (device globals; no runtime allocation) ----------------
__device__ float g_xg[(size_t)BB * TT * G3];   // [B*T][1536] packed input-gate projections
__device__ float g_y0[(size_t)BB * TT * HH];   // [B*T][512] layer-0 tanh outputs
__device__ float g_h[2][BB * HH];              // ping-pong hidden state
__device__ unsigned g_cnt[4];                  // per-batch-group production counters (zero-init)

// ---------------- packed fp32 helpers (fma.rn.f32x2 — sm_103a FFMA2) ----------------
__device__ __forceinline__ void fma2(unsigned long long& d,
                                     unsigned long long a, unsigned long long b) {
    asm("fma.rn.f32x2 %0, %1, %2, %0;" : "+l"(d) : "l"(a), "l"(b));
}
__device__ __forceinline__ unsigned long long pk2(float x, float y) {
    unsigned long long r;
    asm("mov.b64 %0, {%1,%2};" : "=l"(r) : "f"(x), "f"(y));
    return r;
}
__device__ __forceinline__ float2 upk2(unsigned long long v) {
    float2 r;
    asm("mov.b64 {%0,%1}, %2;" : "=f"(r.x), "=f"(r.y) : "l"(v));
    return r;
}

// ---------------- phase A: C[M,1536] = A[M,K] @ W[K,1536] + bias ----------------
__global__ __launch_bounds__(256) void gemm_k(
    const float* __restrict__ A, const float* __restrict__ W,
    const float* __restrict__ bias, float* __restrict__ C, int K)
{
    __shared__ __align__(16) float As[16][136];   // As[k][m]
    __shared__ __align__(16) float Bs[16][128];   // Bs[k][n]
    const int tid = threadIdx.x;
    const int bm = blockIdx.y * 128;
    const int bn = blockIdx.x * 128;
    const int tm = (tid >> 4) << 3;
    const int tn = (tid & 15) << 3;

    const int ar = tid >> 1;           // 0..127 (A row)
    const int ac = (tid & 1) << 3;     // 0 or 8 (k offset)
    const int br = tid >> 5;           // 0..7   (W k row)
    const int bc = (tid & 31) << 2;    // 0..124 (W col)

    unsigned long long acc2[8][4];     // [m][n-pair] packed fp32 pairs
#pragma unroll
    for (int i = 0; i < 8; ++i)
#pragma unroll
        for (int j = 0; j < 4; ++j) acc2[i][j] = 0ull;

    for (int k0 = 0; k0 < K; k0 += 16) {
        float4 a0 = *(const float4*)&A[(size_t)(bm + ar) * K + k0 + ac];
        float4 a1 = *(const float4*)&A[(size_t)(bm + ar) * K + k0 + ac + 4];
        float4 b0 = *(const float4*)&W[(size_t)(k0 + br) * G3 + bn + bc];
        float4 b1 = *(const float4*)&W[(size_t)(k0 + br + 8) * G3 + bn + bc];
        __syncthreads();
        As[ac + 0][ar] = a0.x; As[ac + 1][ar] = a0.y;
        As[ac + 2][ar] = a0.z; As[ac + 3][ar] = a0.w;
        As[ac + 4][ar] = a1.x; As[ac + 5][ar] = a1.y;
        As[ac + 6][ar] = a1.z; As[ac + 7][ar] = a1.w;
        *(float4*)&Bs[br][bc]     = b0;
        *(float4*)&Bs[br + 8][bc] = b1;
        __syncthreads();
#pragma unroll
        for (int kk = 0; kk < 16; ++kk) {
            float4 af0 = *(const float4*)&As[kk][tm];
            float4 af1 = *(const float4*)&As[kk][tm + 4];
            ulonglong2 bq0 = *(const ulonglong2*)&Bs[kk][tn];
            ulonglong2 bq1 = *(const ulonglong2*)&Bs[kk][tn + 4];
            float av[8] = {af0.x, af0.y, af0.z, af0.w, af1.x, af1.y, af1.z, af1.w};
            unsigned long long bv[4] = {bq0.x, bq0.y, bq1.x, bq1.y};
#pragma unroll
            for (int i = 0; i < 8; ++i) {
                unsigned long long ad = pk2(av[i], av[i]);
#pragma unroll
                for (int j = 0; j < 4; ++j)
                    fma2(acc2[i][j], ad, bv[j]);
            }
        }
    }
    float bvv[8];
#pragma unroll
    for (int j = 0; j < 8; ++j) bvv[j] = bias[bn + tn + j];
#pragma unroll
    for (int i = 0; i < 8; ++i) {
        float* cp = &C[(size_t)(bm + tm + i) * G3 + bn + tn];
        float2 p0 = upk2(acc2[i][0]);
        float2 p1 = upk2(acc2[i][1]);
        float2 p2 = upk2(acc2[i][2]);
        float2 p3 = upk2(acc2[i][3]);
        float4 v0 = make_float4(p0.x + bvv[0], p0.y + bvv[1], p1.x + bvv[2], p1.y + bvv[3]);
        float4 v1 = make_float4(p2.x + bvv[4], p2.y + bvv[5], p3.x + bvv[6], p3.y + bvv[7]);
        *(float4*)&cp[0] = v0;
        *(float4*)&cp[4] = v1;
    }
}

// ---------------- phase R: persistent GRU recurrence ----------------
// 128 CTAs = 4 batch-groups(16 batches) x 32 col-groups(16 output cols = 48 gate cols).
// Batch groups are fully independent: sync via per-group counter only.
#define SMEM_R ((48 * WS_PAD + 16 * WS_PAD + 8 * 16 * 16 * 3) * 4)

__device__ __forceinline__ float sigf(float x) { return 1.f / (1.f + expf(-x)); }

__global__ __launch_bounds__(256, 1) void gru_rec(
    const float* __restrict__ Wh,    // [512][1536]
    const float* __restrict__ bhn,   // [512]
    const float* __restrict__ xg,    // [B*T][1536]
    float* __restrict__ y,           // [B*T][512] (y_all=1) or [B][512] last tanh (y_all=0)
    float* __restrict__ cfin,        // [64*512] final raw h
    int y_all)
{
    extern __shared__ __align__(16) float sm[];
    float* Ws  = sm;                       // [48][WS_PAD], row c = g*16 + jl
    float* hs  = Ws + 48 * WS_PAD;         // [16][WS_PAD]
    float* red = hs + 16 * WS_PAD;         // [8 kc][16 b][16 j][3 g]

    const int tid = threadIdx.x;
    const int cta = blockIdx.x;
    const int bg = cta >> 5;               // batch group 0..3
    const int jg = cta & 31;               // col group 0..31
    const int b0 = bg * 16;
    const int j0 = jg * 16;

    // Stage W_h slice once (reused for all 1024 steps).
    for (int i = tid; i < 48 * 512; i += 256) {
        int k = i / 48;
        int c = i % 48;
        int g = c >> 4, jl = c & 15;
        Ws[c * WS_PAD + k] = Wh[(size_t)k * G3 + g * HH + j0 + jl];
    }

    const int jl = tid & 15;
    const int bh = (tid >> 4) & 1;         // batch half (8 each)
    const int kc = tid >> 5;               // K-split / warp id 0..7
    const int kb = kc * 64;
    const int lane = tid & 31;
    const int eb = tid >> 4;               // elementwise batch 0..15
    const int ej = tid & 15;               // elementwise col
    const float bh_n = bhn[j0 + ej];

    // Produce h^(0) = 0 for our own slice, publish like a normal step.
    g_h[0][(size_t)(b0 + eb) * HH + j0 + ej] = 0.f;
    __syncthreads();
    if (tid == 0) { __threadfence(); atomicAdd(&g_cnt[bg], 1u); }

    // Warp-private staging geometry: warp kc stages hs[all 16 b][kb..kb+64).
    const int sb = lane >> 1;              // batch row this lane stages
    const int sk = kb + (lane & 1) * 32;   // 32-float span (8 float4)

    const float* w0p = &Ws[(0 * 16 + jl) * WS_PAD];
    const float* w1p = &Ws[(1 * 16 + jl) * WS_PAD];
    const float* w2p = &Ws[(2 * 16 + jl) * WS_PAD];
    const float* hp  = &hs[bh * 8 * WS_PAD];

    for (int t = 0; t < TT; ++t) {
        const float* hin = g_h[t & 1];
        float* hout = g_h[(t + 1) & 1];

        // xg prefetch (independent of h) — issued before the poll.
        size_t xi = ((size_t)(b0 + eb) * TT + t) * G3 + j0 + ej;
        float xr = __ldcs(&xg[xi]);
        float xz = __ldcs(&xg[xi + 512]);
        float xn = __ldcs(&xg[xi + 1024]);

        // Per-warp wait for h^(t) availability (group counter).
        unsigned target = 32u * (unsigned)(t + 1);
        if (lane == 0) {
            while (*(volatile unsigned*)&g_cnt[bg] < target) __nanosleep(20);
        }
        __syncwarp();

        // Warp-private h staging (exactly the region this warp consumes).
        float4 hv0[8];
#pragma unroll
        for (int u = 0; u < 8; ++u)
            hv0[u] = __ldcg((const float4*)&hin[(size_t)(b0 + sb) * HH + sk + u * 4]);
#pragma unroll
        for (int u = 0; u < 8; ++u)
            *(float4*)&hs[sb * WS_PAD + sk + u * 4] = hv0[u];
        __syncwarp();

        // Partial GEMM: packed fp32 pairs over k. acc2[8 batches][3 gates].
        unsigned long long acc2[8][3];
#pragma unroll
        for (int i = 0; i < 8; ++i)
            acc2[i][0] = acc2[i][1] = acc2[i][2] = 0ull;

#pragma unroll 4
        for (int k4 = kb; k4 < kb + 64; k4 += 4) {
            ulonglong2 w0 = *(const ulonglong2*)&w0p[k4];
            ulonglong2 w1 = *(const ulonglong2*)&w1p[k4];
            ulonglong2 w2 = *(const ulonglong2*)&w2p[k4];
#pragma unroll
            for (int i = 0; i < 8; ++i) {
                ulonglong2 hv = *(const ulonglong2*)&hp[i * WS_PAD + k4];
                fma2(acc2[i][0], hv.x, w0.x); fma2(acc2[i][0], hv.y, w0.y);
                fma2(acc2[i][1], hv.x, w1.x); fma2(acc2[i][1], hv.y, w1.y);
                fma2(acc2[i][2], hv.x, w2.x); fma2(acc2[i][2], hv.y, w2.y);
            }
        }

        // Write K-split partials (horizontal sum of packed halves).
#pragma unroll
        for (int i = 0; i < 8; ++i) {
            int b = bh * 8 + i;
            float* rp = &red[((kc * 16 + b) * 16 + jl) * 3];
            float2 a0 = upk2(acc2[i][0]);
            float2 a1 = upk2(acc2[i][1]);
            float2 a2 = upk2(acc2[i][2]);
            rp[0] = a0.x + a0.y; rp[1] = a1.x + a1.y; rp[2] = a2.x + a2.y;
        }
        __syncthreads();

        // Elementwise GRU update: thread = (eb, ej).
        float hr = 0.f, hz = 0.f, hn = 0.f;
#pragma unroll
        for (int c = 0; c < 8; ++c) {
            const float* rp = &red[((c * 16 + eb) * 16 + ej) * 3];
            hr += rp[0]; hz += rp[1]; hn += rp[2];
        }
        float h_old = hs[eb * WS_PAD + j0 + ej];
        float r = sigf(xr + hr);
        float z = sigf(xz + hz);
        float n = tanhf(xn + r * (hn + bh_n));
        float hnew = (1.f - z) * n + z * h_old;

        hout[(size_t)(b0 + eb) * HH + j0 + ej] = hnew;
        if (y_all) {
            y[((size_t)(b0 + eb) * TT + t) * HH + j0 + ej] = tanhf(hnew);
        } else if (t == TT - 1) {
            y[(size_t)(b0 + eb) * HH + j0 + ej] = tanhf(hnew);
        }
        if (t == TT - 1)
            cfin[(size_t)(b0 + eb) * HH + j0 + ej] = hnew;

        // Publish h^(t+1).
        __syncthreads();
        if (tid == 0) { __threadfence(); atomicAdd(&g_cnt[bg], 1u); }
    }

    // Reset group counter for graph replay (one resetter per group, after all
    // 32*(TT+1) increments have landed).
    if (jg == 0 && tid == 0) {
        unsigned want = 32u * (unsigned)(TT + 1);
        while (*(volatile unsigned*)&g_cnt[bg] < want) __nanosleep(40);
        atomicExch(&g_cnt[bg], 0u);
    }
}

// ---------------- dense head: out = tanh(ylast @ W_out + b_out) ----------------
__global__ __launch_bounds__(256) void dense_k(
    const float* __restrict__ yl,    // [64][512] (already tanh'd)
    const float* __restrict__ W,     // [512][512]
    const float* __restrict__ b,     // [512]
    float* __restrict__ out)         // [64][512]
{
    int gid = blockIdx.x * 256 + threadIdx.x;   // 32768 = 64*512
    int bb = gid >> 9;
    int j  = gid & 511;
    const float* xr = yl + (size_t)bb * 512;
    float s = b[j];
#pragma unroll 4
    for (int k = 0; k < 512; k += 4) {
        float4 xv = *(const float4*)&xr[k];
        s = fmaf(xv.x, W[(size_t)(k + 0) * 512 + j], s);
        s = fmaf(xv.y, W[(size_t)(k + 1) * 512 + j], s);
        s = fmaf(xv.z, W[(size_t)(k + 2) * 512 + j], s);
        s = fmaf(xv.w, W[(size_t)(k + 3) * 512 + j], s);
    }
    out[gid] = tanhf(s);
}

// ---------------- launch ----------------
extern "C" void kernel_launch(void* const* d_in, const int* in_sizes, int n_in,
                              void* d_out, int out_size) {
    const float* x     = (const float*)d_in[0];
    const float* W_i0  = (const float*)d_in[1];
    const float* b_i0  = (const float*)d_in[2];
    const float* W_h0  = (const float*)d_in[3];
    const float* b_hn0 = (const float*)d_in[4];
    const float* W_i1  = (const float*)d_in[5];
    const float* b_i1  = (const float*)d_in[6];
    const float* W_h1  = (const float*)d_in[7];
    const float* b_hn1 = (const float*)d_in[8];
    const float* W_out = (const float*)d_in[9];
    const float* b_out = (const float*)d_in[10];

    float* out = (float*)d_out;               // [64,512]
    float* c0  = out + 64 * 512;              // [64,512]
    float* c1  = c0 + 64 * 512;               // [64,512]

    cudaFuncSetAttribute(gru_rec, cudaFuncAttributeMaxDynamicSharedMemorySize, SMEM_R);

    float* xg;  cudaGetSymbolAddress((void**)&xg, g_xg);
    float* y0;  cudaGetSymbolAddress((void**)&y0, g_y0);

    dim3 ggrid(G3 / 128, (BB * TT) / 128);

    // Layer 0
    gemm_k<<<ggrid, 256>>>(x, W_i0, b_i0, xg, 256);
    gru_rec<<<128, 256, SMEM_R>>>(W_h0, b_hn0, xg, y0, c0, 1);
    // Layer 1
    gemm_k<<<ggrid, 256>>>(y0, W_i1, b_i1, xg, 512);
    gru_rec<<<128, 256, SMEM_R>>>(W_h1, b_hn1, xg, y0 /*last-step tanh*/, c1, 0);
    // Dense head
    dense_k<<<128, 256>>>(y0, W_out, b_out, out);
}

// round 6
// speedup vs baseline: 1.1612x; 1.1061x over previous
#include <cuda_runtime.h>
#include <cstdint>
#include <math.h>

#define BB 64
#define TT 1024
#define HH 512
#define G3 1536
#define WS_PAD 516

// ---------------- scratch (device globals; no runtime allocation) ----------------
__device__ float g_xg[(size_t)BB * TT * G3];   // [B*T][1536] packed input-gate projections
__device__ float g_y0[(size_t)BB * TT * HH];   // [B*T][512] layer-0 tanh outputs
__device__ float g_h[2][BB * HH];              // ping-pong hidden state
__device__ unsigned g_cnt[4];                  // per-batch-group production counters (zero-init)

// ---------------- packed fp32 helpers ----------------
__device__ __forceinline__ void fma2(unsigned long long& d,
                                     unsigned long long a, unsigned long long b) {
    asm("fma.rn.f32x2 %0, %1, %2, %0;" : "+l"(d) : "l"(a), "l"(b));
}
__device__ __forceinline__ float2 upk2(unsigned long long v) {
    float2 r;
    asm("mov.b64 {%0,%1}, %2;" : "=f"(r.x), "=f"(r.y) : "l"(v));
    return r;
}

// ---------------- tf32 helpers ----------------
__device__ __forceinline__ uint32_t to_tf32(float x) {
    uint32_t r;
    asm("cvt.rna.tf32.f32 %0, %1;" : "=r"(r) : "f"(x));
    return r;
}
#define MMA_TF32(d, a, b)                                                        \
    asm volatile("mma.sync.aligned.m16n8k8.row.col.f32.tf32.tf32.f32 "           \
                 "{%0,%1,%2,%3},{%4,%5,%6,%7},{%8,%9},{%0,%1,%2,%3};"            \
                 : "+f"((d)[0]), "+f"((d)[1]), "+f"((d)[2]), "+f"((d)[3])        \
                 : "r"((a)[0]), "r"((a)[1]), "r"((a)[2]), "r"((a)[3]),           \
                   "r"((b)[0]), "r"((b)[1]))

// ---------------- phase A: C[M,1536] = A[M,K] @ W[K,1536] + bias (tf32 MMA) ----------------
// CTA tile 128x128, K-tile 16. 8 warps: wm = wid&1 (2 x 64 rows), wn = wid>>1 (4 x 32 cols).
__global__ __launch_bounds__(256) void gemm_tf32(
    const float* __restrict__ A, const float* __restrict__ W,
    const float* __restrict__ bias, float* __restrict__ C, int K)
{
    __shared__ uint32_t As[128][20];   // [m][k] tf32, pad to 20 words
    __shared__ uint32_t Bs[16][136];   // [k][n] tf32, pad to 136 words

    const int tid = threadIdx.x;
    const int lane = tid & 31;
    const int wid = tid >> 5;
    const int wm = wid & 1;
    const int wn = wid >> 1;
    const int g = lane >> 2;
    const int c = lane & 3;
    const int bm = blockIdx.y * 128;
    const int bn = blockIdx.x * 128;

    // staging geometry
    const int ar = tid >> 1;            // A row 0..127
    const int ak = (tid & 1) * 8;       // A k offset 0/8
    const int br = tid >> 4;            // B k row 0..15
    const int bc = (tid & 15) * 8;      // B col offset

    float acc[4][4][4];
#pragma unroll
    for (int mt = 0; mt < 4; ++mt)
#pragma unroll
        for (int nt = 0; nt < 4; ++nt)
#pragma unroll
            for (int i = 0; i < 4; ++i) acc[mt][nt][i] = 0.f;

    for (int k0 = 0; k0 < K; k0 += 16) {
        float4 a0 = *(const float4*)&A[(size_t)(bm + ar) * K + k0 + ak];
        float4 a1 = *(const float4*)&A[(size_t)(bm + ar) * K + k0 + ak + 4];
        float4 b0 = *(const float4*)&W[(size_t)(k0 + br) * G3 + bn + bc];
        float4 b1 = *(const float4*)&W[(size_t)(k0 + br) * G3 + bn + bc + 4];
        __syncthreads();
        As[ar][ak + 0] = to_tf32(a0.x); As[ar][ak + 1] = to_tf32(a0.y);
        As[ar][ak + 2] = to_tf32(a0.z); As[ar][ak + 3] = to_tf32(a0.w);
        As[ar][ak + 4] = to_tf32(a1.x); As[ar][ak + 5] = to_tf32(a1.y);
        As[ar][ak + 6] = to_tf32(a1.z); As[ar][ak + 7] = to_tf32(a1.w);
        Bs[br][bc + 0] = to_tf32(b0.x); Bs[br][bc + 1] = to_tf32(b0.y);
        Bs[br][bc + 2] = to_tf32(b0.z); Bs[br][bc + 3] = to_tf32(b0.w);
        Bs[br][bc + 4] = to_tf32(b1.x); Bs[br][bc + 5] = to_tf32(b1.y);
        Bs[br][bc + 6] = to_tf32(b1.z); Bs[br][bc + 7] = to_tf32(b1.w);
        __syncthreads();

#pragma unroll
        for (int kk = 0; kk < 2; ++kk) {
            uint32_t afr[4][4];
#pragma unroll
            for (int mt = 0; mt < 4; ++mt) {
                int arow = wm * 64 + mt * 16 + g;
                afr[mt][0] = As[arow][kk * 8 + c];
                afr[mt][1] = As[arow + 8][kk * 8 + c];
                afr[mt][2] = As[arow][kk * 8 + c + 4];
                afr[mt][3] = As[arow + 8][kk * 8 + c + 4];
            }
            uint32_t bfr[4][2];
#pragma unroll
            for (int nt = 0; nt < 4; ++nt) {
                int bcol = wn * 32 + nt * 8 + g;
                bfr[nt][0] = Bs[kk * 8 + c][bcol];
                bfr[nt][1] = Bs[kk * 8 + c + 4][bcol];
            }
#pragma unroll
            for (int mt = 0; mt < 4; ++mt)
#pragma unroll
                for (int nt = 0; nt < 4; ++nt)
                    MMA_TF32(acc[mt][nt], afr[mt], bfr[nt]);
        }
    }

    // epilogue: D rows = bm + wm*64 + mt*16 + g(+8); cols = bn + wn*32 + nt*8 + 2c
#pragma unroll
    for (int mt = 0; mt < 4; ++mt) {
        int r0 = bm + wm * 64 + mt * 16 + g;
#pragma unroll
        for (int nt = 0; nt < 4; ++nt) {
            int col = bn + wn * 32 + nt * 8 + 2 * c;
            float2 bv = *(const float2*)&bias[col];
            float2 v0 = make_float2(acc[mt][nt][0] + bv.x, acc[mt][nt][1] + bv.y);
            float2 v1 = make_float2(acc[mt][nt][2] + bv.x, acc[mt][nt][3] + bv.y);
            *(float2*)&C[(size_t)r0 * G3 + col] = v0;
            *(float2*)&C[(size_t)(r0 + 8) * G3 + col] = v1;
        }
    }
}

// ---------------- phase R: persistent GRU recurrence ----------------
// 128 CTAs = 4 batch-groups(16 batches) x 32 col-groups(16 output cols = 48 gate cols).
#define SMEM_R ((48 * WS_PAD + 16 * WS_PAD + 8 * 16 * 16 * 3) * 4)

__device__ __forceinline__ float sigf(float x) {
    return __fdividef(1.f, 1.f + __expf(-x));
}

__global__ __launch_bounds__(256, 1) void gru_rec(
    const float* __restrict__ Wh,    // [512][1536]
    const float* __restrict__ bhn,   // [512]
    const float* __restrict__ xg,    // [B*T][1536]
    float* __restrict__ y,           // [B*T][512] (y_all=1) or [B][512] last tanh (y_all=0)
    float* __restrict__ cfin,        // [64*512] final raw h
    int y_all)
{
    extern __shared__ __align__(16) float sm[];
    float* Ws  = sm;                       // [48][WS_PAD], row c = g*16 + jl
    float* hs  = Ws + 48 * WS_PAD;         // [16][WS_PAD]
    float* red = hs + 16 * WS_PAD;         // [8 kc][16 b][16 j][3 g]

    const int tid = threadIdx.x;
    const int cta = blockIdx.x;
    const int bg = cta >> 5;               // batch group 0..3
    const int jg = cta & 31;               // col group 0..31
    const int b0 = bg * 16;
    const int j0 = jg * 16;

    // Stage W_h slice once (reused for all 1024 steps).
    for (int i = tid; i < 48 * 512; i += 256) {
        int k = i / 48;
        int c = i % 48;
        int g = c >> 4, jl = c & 15;
        Ws[c * WS_PAD + k] = Wh[(size_t)k * G3 + g * HH + j0 + jl];
    }

    const int jl = tid & 15;
    const int bh = (tid >> 4) & 1;         // batch half (8 each)
    const int kc = tid >> 5;               // K-split / warp id 0..7
    const int kb = kc * 64;
    const int lane = tid & 31;
    const int eb = tid >> 4;               // elementwise batch 0..15
    const int ej = tid & 15;               // elementwise col
    const float bh_n = bhn[j0 + ej];

    // Produce h^(0) = 0 for our own slice, publish like a normal step.
    g_h[0][(size_t)(b0 + eb) * HH + j0 + ej] = 0.f;
    __syncthreads();
    if (tid == 0) { __threadfence(); atomicAdd(&g_cnt[bg], 1u); }

    // Warp-private staging geometry: warp kc stages hs[all 16 b][kb..kb+64).
    const int sb = lane >> 1;              // batch row this lane stages
    const int sk = kb + (lane & 1) * 32;   // 32-float span (8 float4)

    const float* w0p = &Ws[(0 * 16 + jl) * WS_PAD];
    const float* w1p = &Ws[(1 * 16 + jl) * WS_PAD];
    const float* w2p = &Ws[(2 * 16 + jl) * WS_PAD];
    const float* hp  = &hs[bh * 8 * WS_PAD];

    for (int t = 0; t < TT; ++t) {
        const float* hin = g_h[t & 1];
        float* hout = g_h[(t + 1) & 1];

        // xg prefetch (independent of h) — issued before the poll.
        size_t xi = ((size_t)(b0 + eb) * TT + t) * G3 + j0 + ej;
        float xr = __ldcs(&xg[xi]);
        float xz = __ldcs(&xg[xi + 512]);
        float xn = __ldcs(&xg[xi + 1024]);

        // Per-warp wait for h^(t) availability (tight poll, no sleep).
        unsigned target = 32u * (unsigned)(t + 1);
        if (lane == 0) {
            while (*(volatile unsigned*)&g_cnt[bg] < target) { }
        }
        __syncwarp();

        // Warp-private h staging (exactly the region this warp consumes).
        float4 hv0[8];
#pragma unroll
        for (int u = 0; u < 8; ++u)
            hv0[u] = __ldcg((const float4*)&hin[(size_t)(b0 + sb) * HH + sk + u * 4]);
#pragma unroll
        for (int u = 0; u < 8; ++u)
            *(float4*)&hs[sb * WS_PAD + sk + u * 4] = hv0[u];
        __syncwarp();

        // Partial GEMM: packed fp32 pairs over k. acc2[8 batches][3 gates].
        unsigned long long acc2[8][3];
#pragma unroll
        for (int i = 0; i < 8; ++i)
            acc2[i][0] = acc2[i][1] = acc2[i][2] = 0ull;

#pragma unroll 4
        for (int k4 = kb; k4 < kb + 64; k4 += 4) {
            ulonglong2 w0 = *(const ulonglong2*)&w0p[k4];
            ulonglong2 w1 = *(const ulonglong2*)&w1p[k4];
            ulonglong2 w2 = *(const ulonglong2*)&w2p[k4];
#pragma unroll
            for (int i = 0; i < 8; ++i) {
                ulonglong2 hv = *(const ulonglong2*)&hp[i * WS_PAD + k4];
                fma2(acc2[i][0], hv.x, w0.x); fma2(acc2[i][0], hv.y, w0.y);
                fma2(acc2[i][1], hv.x, w1.x); fma2(acc2[i][1], hv.y, w1.y);
                fma2(acc2[i][2], hv.x, w2.x); fma2(acc2[i][2], hv.y, w2.y);
            }
        }

        // Write K-split partials (horizontal sum of packed halves).
#pragma unroll
        for (int i = 0; i < 8; ++i) {
            int b = bh * 8 + i;
            float* rp = &red[((kc * 16 + b) * 16 + jl) * 3];
            float2 a0 = upk2(acc2[i][0]);
            float2 a1 = upk2(acc2[i][1]);
            float2 a2 = upk2(acc2[i][2]);
            rp[0] = a0.x + a0.y; rp[1] = a1.x + a1.y; rp[2] = a2.x + a2.y;
        }
        __syncthreads();

        // Elementwise GRU update: thread = (eb, ej).
        float hr = 0.f, hz = 0.f, hn = 0.f;
#pragma unroll
        for (int c = 0; c < 8; ++c) {
            const float* rp = &red[((c * 16 + eb) * 16 + ej) * 3];
            hr += rp[0]; hz += rp[1]; hn += rp[2];
        }
        float h_old = hs[eb * WS_PAD + j0 + ej];
        float r = sigf(xr + hr);
        float z = sigf(xz + hz);
        float n = tanhf(xn + r * (hn + bh_n));
        float hnew = (1.f - z) * n + z * h_old;

        hout[(size_t)(b0 + eb) * HH + j0 + ej] = hnew;

        // Publish h^(t+1), then do the non-critical stores.
        __syncthreads();
        if (tid == 0) { __threadfence(); atomicAdd(&g_cnt[bg], 1u); }

        if (y_all) {
            y[((size_t)(b0 + eb) * TT + t) * HH + j0 + ej] = tanhf(hnew);
        } else if (t == TT - 1) {
            y[(size_t)(b0 + eb) * HH + j0 + ej] = tanhf(hnew);
        }
        if (t == TT - 1)
            cfin[(size_t)(b0 + eb) * HH + j0 + ej] = hnew;
    }

    // Reset group counter for graph replay.
    if (jg == 0 && tid == 0) {
        unsigned want = 32u * (unsigned)(TT + 1);
        while (*(volatile unsigned*)&g_cnt[bg] < want) __nanosleep(40);
        atomicExch(&g_cnt[bg], 0u);
    }
}

// ---------------- dense head: out = tanh(ylast @ W_out + b_out) ----------------
__global__ __launch_bounds__(256) void dense_k(
    const float* __restrict__ yl,    // [64][512] (already tanh'd)
    const float* __restrict__ W,     // [512][512]
    const float* __restrict__ b,     // [512]
    float* __restrict__ out)         // [64][512]
{
    int gid = blockIdx.x * 256 + threadIdx.x;   // 32768 = 64*512
    int bb = gid >> 9;
    int j  = gid & 511;
    const float* xr = yl + (size_t)bb * 512;
    float s = b[j];
#pragma unroll 4
    for (int k = 0; k < 512; k += 4) {
        float4 xv = *(const float4*)&xr[k];
        s = fmaf(xv.x, W[(size_t)(k + 0) * 512 + j], s);
        s = fmaf(xv.y, W[(size_t)(k + 1) * 512 + j], s);
        s = fmaf(xv.z, W[(size_t)(k + 2) * 512 + j], s);
        s = fmaf(xv.w, W[(size_t)(k + 3) * 512 + j], s);
    }
    out[gid] = tanhf(s);
}

// ---------------- launch ----------------
extern "C" void kernel_launch(void* const* d_in, const int* in_sizes, int n_in,
                              void* d_out, int out_size) {
    const float* x     = (const float*)d_in[0];
    const float* W_i0  = (const float*)d_in[1];
    const float* b_i0  = (const float*)d_in[2];
    const float* W_h0  = (const float*)d_in[3];
    const float* b_hn0 = (const float*)d_in[4];
    const float* W_i1  = (const float*)d_in[5];
    const float* b_i1  = (const float*)d_in[6];
    const float* W_h1  = (const float*)d_in[7];
    const float* b_hn1 = (const float*)d_in[8];
    const float* W_out = (const float*)d_in[9];
    const float* b_out = (const float*)d_in[10];

    float* out = (float*)d_out;               // [64,512]
    float* c0  = out + 64 * 512;              // [64,512]
    float* c1  = c0 + 64 * 512;               // [64,512]

    cudaFuncSetAttribute(gru_rec, cudaFuncAttributeMaxDynamicSharedMemorySize, SMEM_R);

    float* xg;  cudaGetSymbolAddress((void**)&xg, g_xg);
    float* y0;  cudaGetSymbolAddress((void**)&y0, g_y0);

    dim3 ggrid(G3 / 128, (BB * TT) / 128);

    // Layer 0
    gemm_tf32<<<ggrid, 256>>>(x, W_i0, b_i0, xg, 256);
    gru_rec<<<128, 256, SMEM_R>>>(W_h0, b_hn0, xg, y0, c0, 1);
    // Layer 1
    gemm_tf32<<<ggrid, 256>>>(y0, W_i1, b_i1, xg, 512);
    gru_rec<<<128, 256, SMEM_R>>>(W_h1, b_hn1, xg, y0 /*last-step tanh*/, c1, 0);
    // Dense head
    dense_k<<<128, 256>>>(y0, W_out, b_out, out);
}

// round 8
// speedup vs baseline: 2.0796x; 1.7909x over previous
#include <cuda_runtime.h>
#include <cuda_fp16.h>
#include <cstdint>
#include <math.h>

#define BB 64
#define TT 1024
#define HH 512
#define G3 1536
#define HPAD 516

// ---------------- scratch (device globals; no runtime allocation) ----------------
__device__ float g_xg[(size_t)BB * TT * G3];   // [B*T][1536] packed input-gate projections
__device__ float g_y0[(size_t)BB * TT * HH];   // [B*T][512] layer-0 tanh outputs
__device__ float g_h[2][BB * HH];              // ping-pong hidden state
__device__ unsigned g_cnt[4];                  // per-batch-group production counters (zero-init)

// ---------------- tf32 helpers (phase A) ----------------
__device__ __forceinline__ uint32_t to_tf32(float x) {
    uint32_t r;
    asm("cvt.rna.tf32.f32 %0, %1;" : "=r"(r) : "f"(x));
    return r;
}
#define MMA_TF32(d, a, b)                                                        \
    asm volatile("mma.sync.aligned.m16n8k8.row.col.f32.tf32.tf32.f32 "           \
                 "{%0,%1,%2,%3},{%4,%5,%6,%7},{%8,%9},{%0,%1,%2,%3};"            \
                 : "+f"((d)[0]), "+f"((d)[1]), "+f"((d)[2]), "+f"((d)[3])        \
                 : "r"((a)[0]), "r"((a)[1]), "r"((a)[2]), "r"((a)[3]),           \
                   "r"((b)[0]), "r"((b)[1]))

// ---------------- fp16 mma helper (phase R) ----------------
#define MMA_F16(d, a, b)                                                         \
    asm volatile("mma.sync.aligned.m16n8k16.row.col.f32.f16.f16.f32 "            \
                 "{%0,%1,%2,%3},{%4,%5,%6,%7},{%8,%9},{%0,%1,%2,%3};"            \
                 : "+f"((d)[0]), "+f"((d)[1]), "+f"((d)[2]), "+f"((d)[3])        \
                 : "r"((a)[0]), "r"((a)[1]), "r"((a)[2]), "r"((a)[3]),           \
                   "r"((b)[0]), "r"((b)[1]))

__device__ __forceinline__ unsigned poll_acq(const unsigned* p) {
    unsigned v;
    asm volatile("ld.acquire.gpu.global.u32 %0, [%1];" : "=r"(v) : "l"(p) : "memory");
    return v;
}

// split a float2 into fp16x2 hi and lo (two-term split; residual exact)
__device__ __forceinline__ void split2(float2 v, uint32_t& hi, uint32_t& lo) {
    __half2 h2 = __floats2half2_rn(v.x, v.y);
    float2 hf = __half22float2(h2);
    __half2 l2 = __floats2half2_rn(v.x - hf.x, v.y - hf.y);
    hi = *(uint32_t*)&h2;
    lo = *(uint32_t*)&l2;
}

// ---------------- phase A: C[M,1536] = A[M,K] @ W[K,1536] + bias (tf32 MMA) ----------------
__global__ __launch_bounds__(256) void gemm_tf32(
    const float* __restrict__ A, const float* __restrict__ W,
    const float* __restrict__ bias, float* __restrict__ C, int K)
{
    __shared__ uint32_t As[128][20];
    __shared__ uint32_t Bs[16][136];

    const int tid = threadIdx.x;
    const int lane = tid & 31;
    const int wid = tid >> 5;
    const int wm = wid & 1;
    const int wn = wid >> 1;
    const int g = lane >> 2;
    const int c = lane & 3;
    const int bm = blockIdx.y * 128;
    const int bn = blockIdx.x * 128;

    const int ar = tid >> 1;
    const int ak = (tid & 1) * 8;
    const int br = tid >> 4;
    const int bc = (tid & 15) * 8;

    float acc[4][4][4];
#pragma unroll
    for (int mt = 0; mt < 4; ++mt)
#pragma unroll
        for (int nt = 0; nt < 4; ++nt)
#pragma unroll
            for (int i = 0; i < 4; ++i) acc[mt][nt][i] = 0.f;

    for (int k0 = 0; k0 < K; k0 += 16) {
        float4 a0 = *(const float4*)&A[(size_t)(bm + ar) * K + k0 + ak];
        float4 a1 = *(const float4*)&A[(size_t)(bm + ar) * K + k0 + ak + 4];
        float4 b0 = *(const float4*)&W[(size_t)(k0 + br) * G3 + bn + bc];
        float4 b1 = *(const float4*)&W[(size_t)(k0 + br) * G3 + bn + bc + 4];
        __syncthreads();
        As[ar][ak + 0] = to_tf32(a0.x); As[ar][ak + 1] = to_tf32(a0.y);
        As[ar][ak + 2] = to_tf32(a0.z); As[ar][ak + 3] = to_tf32(a0.w);
        As[ar][ak + 4] = to_tf32(a1.x); As[ar][ak + 5] = to_tf32(a1.y);
        As[ar][ak + 6] = to_tf32(a1.z); As[ar][ak + 7] = to_tf32(a1.w);
        Bs[br][bc + 0] = to_tf32(b0.x); Bs[br][bc + 1] = to_tf32(b0.y);
        Bs[br][bc + 2] = to_tf32(b0.z); Bs[br][bc + 3] = to_tf32(b0.w);
        Bs[br][bc + 4] = to_tf32(b1.x); Bs[br][bc + 5] = to_tf32(b1.y);
        Bs[br][bc + 6] = to_tf32(b1.z); Bs[br][bc + 7] = to_tf32(b1.w);
        __syncthreads();

#pragma unroll
        for (int kk = 0; kk < 2; ++kk) {
            uint32_t afr[4][4];
#pragma unroll
            for (int mt = 0; mt < 4; ++mt) {
                int arow = wm * 64 + mt * 16 + g;
                afr[mt][0] = As[arow][kk * 8 + c];
                afr[mt][1] = As[arow + 8][kk * 8 + c];
                afr[mt][2] = As[arow][kk * 8 + c + 4];
                afr[mt][3] = As[arow + 8][kk * 8 + c + 4];
            }
            uint32_t bfr[4][2];
#pragma unroll
            for (int nt = 0; nt < 4; ++nt) {
                int bcol = wn * 32 + nt * 8 + g;
                bfr[nt][0] = Bs[kk * 8 + c][bcol];
                bfr[nt][1] = Bs[kk * 8 + c + 4][bcol];
            }
#pragma unroll
            for (int mt = 0; mt < 4; ++mt)
#pragma unroll
                for (int nt = 0; nt < 4; ++nt)
                    MMA_TF32(acc[mt][nt], afr[mt], bfr[nt]);
        }
    }

#pragma unroll
    for (int mt = 0; mt < 4; ++mt) {
        int r0 = bm + wm * 64 + mt * 16 + g;
#pragma unroll
        for (int nt = 0; nt < 4; ++nt) {
            int col = bn + wn * 32 + nt * 8 + 2 * c;
            float2 bv = *(const float2*)&bias[col];
            float2 v0 = make_float2(acc[mt][nt][0] + bv.x, acc[mt][nt][1] + bv.y);
            float2 v1 = make_float2(acc[mt][nt][2] + bv.x, acc[mt][nt][3] + bv.y);
            *(float2*)&C[(size_t)r0 * G3 + col] = v0;
            *(float2*)&C[(size_t)(r0 + 8) * G3 + col] = v1;
        }
    }
}

// ---------------- phase R: persistent GRU recurrence (fp16-split tensor cores) ----------------
// 128 CTAs = 4 batch-groups(16 batches) x 32 col-groups(16 output cols = 48 gate cols).
// Per CTA: M=16 (batch), N=48 (gate cols, c = g*16+jl), K=512. Warps split K (64 each).
// W_h fragments (hi+lo fp16) precomputed into registers once; 3 mma terms per tile.
#define SMEM_R ((16 * HPAD + 8 * 16 * 48) * 4)

__device__ __forceinline__ float sigf(float x) {
    return __fdividef(1.f, 1.f + __expf(-x));
}

__global__ __launch_bounds__(256, 1) void gru_rec(
    const float* __restrict__ Wh,    // [512][1536]
    const float* __restrict__ bhn,   // [512]
    const float* __restrict__ xg,    // [B*T][1536]
    float* __restrict__ y,           // [B*T][512] (y_all=1) or [B][512] last tanh (y_all=0)
    float* __restrict__ cfin,        // [64*512] final raw h
    int y_all)
{
    extern __shared__ __align__(16) float sm[];
    float* hs  = sm;                       // [16][HPAD] staged h (fp32)
    float* red = hs + 16 * HPAD;           // [8 kc][16 row][48 col]

    const int tid = threadIdx.x;
    const int cta = blockIdx.x;
    const int bg = cta >> 5;               // batch group 0..3
    const int jg = cta & 31;               // col group 0..31
    const int b0 = bg * 16;
    const int j0 = jg * 16;

    const int lane = tid & 31;
    const int kc = tid >> 5;               // warp id = K-chunk 0..7
    const int kb = kc * 64;
    const int g = lane >> 2;               // mma group row
    const int c = lane & 3;                // mma group col
    const int eb = tid >> 4;               // elementwise batch 0..15
    const int ej = tid & 15;               // elementwise col
    const float bh_n = bhn[j0 + ej];

    // ---- Precompute W_h fragments (hi/lo fp16) into registers.
    // B-frag m16n8k16 col: b0=(2c,n), b1=(2c+1,n), b2=(2c+8,n), b3=(2c+9,n), n = nt*8+g.
    uint32_t bhi[6][4][2], blo[6][4][2];
#pragma unroll
    for (int nt = 0; nt < 6; ++nt) {
        int cl = nt * 8 + g;               // local col 0..47
        int wcol = (cl >> 4) * HH + j0 + (cl & 15);
#pragma unroll
        for (int kt = 0; kt < 4; ++kt) {
            int kbase = kb + kt * 16;
            float w0 = Wh[(size_t)(kbase + 2 * c) * G3 + wcol];
            float w1 = Wh[(size_t)(kbase + 2 * c + 1) * G3 + wcol];
            float w2 = Wh[(size_t)(kbase + 2 * c + 8) * G3 + wcol];
            float w3 = Wh[(size_t)(kbase + 2 * c + 9) * G3 + wcol];
            split2(make_float2(w0, w1), bhi[nt][kt][0], blo[nt][kt][0]);
            split2(make_float2(w2, w3), bhi[nt][kt][1], blo[nt][kt][1]);
        }
    }

    // Produce h^(0) = 0 for our own slice, publish like a normal step.
    g_h[0][(size_t)(b0 + eb) * HH + j0 + ej] = 0.f;
    __syncthreads();
    if (tid == 0) { __threadfence(); atomicAdd(&g_cnt[bg], 1u); }

    // Warp-private staging: warp kc stages hs[all 16 rows][kb..kb+64).
    const int sb = lane >> 1;
    const int sk = kb + (lane & 1) * 32;

    for (int t = 0; t < TT; ++t) {
        const float* hin = g_h[t & 1];
        float* hout = g_h[(t + 1) & 1];

        // xg prefetch (independent of h) — issued before the poll.
        size_t xi = ((size_t)(b0 + eb) * TT + t) * G3 + j0 + ej;
        float xr = __ldcs(&xg[xi]);
        float xz = __ldcs(&xg[xi + 512]);
        float xn = __ldcs(&xg[xi + 1024]);

        // Per-warp wait for h^(t) availability.
        unsigned target = 32u * (unsigned)(t + 1);
        if (lane == 0) {
            while (poll_acq(&g_cnt[bg]) < target) { }
        }
        __syncwarp();

        // Warp-private h staging (exactly the K-chunk this warp consumes).
        float4 hv0[8];
#pragma unroll
        for (int u = 0; u < 8; ++u)
            hv0[u] = __ldcg((const float4*)&hin[(size_t)(b0 + sb) * HH + sk + u * 4]);
#pragma unroll
        for (int u = 0; u < 8; ++u)
            *(float4*)&hs[sb * HPAD + sk + u * 4] = hv0[u];
        __syncwarp();

        // ---- tensor-core partial GEMM over K-chunk 64: acc[6 n-tiles][4].
        float acc[6][4];
#pragma unroll
        for (int nt = 0; nt < 6; ++nt)
#pragma unroll
            for (int i = 0; i < 4; ++i) acc[nt][i] = 0.f;

#pragma unroll
        for (int kt = 0; kt < 4; ++kt) {
            int k0 = kb + kt * 16;
            // A-frag m16k16: a0,a1=(g,2c..), a2,a3=(g+8,2c..), a4..=(.,2c+8..)
            uint32_t ahi[4], alo[4];
            float2 p0 = *(const float2*)&hs[g * HPAD + k0 + 2 * c];
            float2 p1 = *(const float2*)&hs[(g + 8) * HPAD + k0 + 2 * c];
            float2 p2 = *(const float2*)&hs[g * HPAD + k0 + 2 * c + 8];
            float2 p3 = *(const float2*)&hs[(g + 8) * HPAD + k0 + 2 * c + 8];
            split2(p0, ahi[0], alo[0]);
            split2(p1, ahi[1], alo[1]);
            split2(p2, ahi[2], alo[2]);
            split2(p3, ahi[3], alo[3]);
#pragma unroll
            for (int nt = 0; nt < 6; ++nt) {
                MMA_F16(acc[nt], ahi, bhi[nt][kt]);
                MMA_F16(acc[nt], ahi, blo[nt][kt]);
                MMA_F16(acc[nt], alo, bhi[nt][kt]);
            }
        }

        // Write K-split partials: D frag c0,c1=(g,2c..2c+1), c2,c3=(g+8,..).
#pragma unroll
        for (int nt = 0; nt < 6; ++nt) {
            int colb = nt * 8 + 2 * c;
            *(float2*)&red[(kc * 16 + g) * 48 + colb] =
                make_float2(acc[nt][0], acc[nt][1]);
            *(float2*)&red[(kc * 16 + g + 8) * 48 + colb] =
                make_float2(acc[nt][2], acc[nt][3]);
        }
        __syncthreads();

        // Elementwise GRU update: thread = (eb, ej); gate cols r=ej, z=16+ej, n=32+ej.
        float hr = 0.f, hz = 0.f, hn = 0.f;
#pragma unroll
        for (int q = 0; q < 8; ++q) {
            const float* rp = &red[(q * 16 + eb) * 48];
            hr += rp[ej]; hz += rp[16 + ej]; hn += rp[32 + ej];
        }
        float h_old = hs[eb * HPAD + j0 + ej];
        float r = sigf(xr + hr);
        float z = sigf(xz + hz);
        float n = tanhf(xn + r * (hn + bh_n));
        float hnew = (1.f - z) * n + z * h_old;

        hout[(size_t)(b0 + eb) * HH + j0 + ej] = hnew;

        // Publish h^(t+1), then do the non-critical stores.
        __syncthreads();
        if (tid == 0) { __threadfence(); atomicAdd(&g_cnt[bg], 1u); }

        if (y_all) {
            y[((size_t)(b0 + eb) * TT + t) * HH + j0 + ej] = tanhf(hnew);
        } else if (t == TT - 1) {
            y[(size_t)(b0 + eb) * HH + j0 + ej] = tanhf(hnew);
        }
        if (t == TT - 1)
            cfin[(size_t)(b0 + eb) * HH + j0 + ej] = hnew;
    }

    // Reset group counter for graph replay.
    if (jg == 0 && tid == 0) {
        unsigned want = 32u * (unsigned)(TT + 1);
        while (poll_acq(&g_cnt[bg]) < want) __nanosleep(40);
        atomicExch(&g_cnt[bg], 0u);
    }
}

// ---------------- dense head: out = tanh(ylast @ W_out + b_out) ----------------
__global__ __launch_bounds__(256) void dense_k(
    const float* __restrict__ yl,
    const float* __restrict__ W,
    const float* __restrict__ b,
    float* __restrict__ out)
{
    int gid = blockIdx.x * 256 + threadIdx.x;
    int bb = gid >> 9;
    int j  = gid & 511;
    const float* xr = yl + (size_t)bb * 512;
    float s = b[j];
#pragma unroll 4
    for (int k = 0; k < 512; k += 4) {
        float4 xv = *(const float4*)&xr[k];
        s = fmaf(xv.x, W[(size_t)(k + 0) * 512 + j], s);
        s = fmaf(xv.y, W[(size_t)(k + 1) * 512 + j], s);
        s = fmaf(xv.z, W[(size_t)(k + 2) * 512 + j], s);
        s = fmaf(xv.w, W[(size_t)(k + 3) * 512 + j], s);
    }
    out[gid] = tanhf(s);
}

// ---------------- launch ----------------
extern "C" void kernel_launch(void* const* d_in, const int* in_sizes, int n_in,
                              void* d_out, int out_size) {
    const float* x     = (const float*)d_in[0];
    const float* W_i0  = (const float*)d_in[1];
    const float* b_i0  = (const float*)d_in[2];
    const float* W_h0  = (const float*)d_in[3];
    const float* b_hn0 = (const float*)d_in[4];
    const float* W_i1  = (const float*)d_in[5];
    const float* b_i1  = (const float*)d_in[6];
    const float* W_h1  = (const float*)d_in[7];
    const float* b_hn1 = (const float*)d_in[8];
    const float* W_out = (const float*)d_in[9];
    const float* b_out = (const float*)d_in[10];

    float* out = (float*)d_out;               // [64,512]
    float* c0  = out + 64 * 512;              // [64,512]
    float* c1  = c0 + 64 * 512;               // [64,512]

    cudaFuncSetAttribute(gru_rec, cudaFuncAttributeMaxDynamicSharedMemorySize, SMEM_R);

    float* xg;  cudaGetSymbolAddress((void**)&xg, g_xg);
    float* y0;  cudaGetSymbolAddress((void**)&y0, g_y0);

    dim3 ggrid(G3 / 128, (BB * TT) / 128);

    // Layer 0
    gemm_tf32<<<ggrid, 256>>>(x, W_i0, b_i0, xg, 256);
    gru_rec<<<128, 256, SMEM_R>>>(W_h0, b_hn0, xg, y0, c0, 1);
    // Layer 1
    gemm_tf32<<<ggrid, 256>>>(y0, W_i1, b_i1, xg, 512);
    gru_rec<<<128, 256, SMEM_R>>>(W_h1, b_hn1, xg, y0 /*last-step tanh*/, c1, 0);
    // Dense head
    dense_k<<<128, 256>>>(y0, W_out, b_out, out);
}